// round 1
// baseline (speedup 1.0000x reference)
#include <cuda_runtime.h>
#include <cuda_bf16.h>
#include <stdint.h>

#define NROWS 65536
#define KDIM  2048
#define NCAT  384

#define BM 128
#define BN 64
#define BK 32
#define NKT (KDIM / BK)   // 64

// ---------------- device scratch (no allocation allowed) ----------------
__device__ float g_W1cat[KDIM * NCAT];          // 3 MB, tf32-rounded
__device__ float g_b1cat[NCAT];
__device__ float g_Y1[(size_t)NROWS * NCAT];    // 96 MB

// ---------------- prep: concat + tf32-round W1, concat b1 ----------------
__global__ void prep_kernel(const float* __restrict__ W1_sc, const float* __restrict__ b1_sc,
                            const float* __restrict__ W1_st, const float* __restrict__ b1_st,
                            const float* __restrict__ W1_wm, const float* __restrict__ b1_wm,
                            const float* __restrict__ W1_ch, const float* __restrict__ b1_ch) {
    int total = KDIM * NCAT;
    for (int idx = blockIdx.x * blockDim.x + threadIdx.x; idx < total;
         idx += gridDim.x * blockDim.x) {
        int k = idx / NCAT, n = idx - k * NCAT;
        float v;
        if (n < 64)        v = W1_sc[k * 64 + n];
        else if (n < 128)  v = W1_st[k * 64 + (n - 64)];
        else if (n < 256)  v = W1_wm[(size_t)k * 128 + (n - 128)];
        else               v = W1_ch[(size_t)k * 128 + (n - 256)];
        uint32_t u;
        asm("cvt.rna.tf32.f32 %0, %1;" : "=r"(u) : "f"(v));
        g_W1cat[idx] = __uint_as_float(u);
    }
    if (blockIdx.x == 0 && threadIdx.x < NCAT) {
        int n = threadIdx.x;
        float b = (n < 64)  ? b1_sc[n]
                : (n < 128) ? b1_st[n - 64]
                : (n < 256) ? b1_wm[n - 128]
                :             b1_ch[n - 256];
        g_b1cat[n] = b;
    }
}

// ---------------- stage 1: Y1 = relu(X @ W1cat + b1cat), tf32 mma ----------------
__device__ __forceinline__ void cp16(float* dst, const float* src) {
    uint32_t d = (uint32_t)__cvta_generic_to_shared(dst);
    asm volatile("cp.async.ca.shared.global [%0], [%1], 16;\n" :: "r"(d), "l"(src));
}

__global__ __launch_bounds__(256) void gemm1_kernel(const float* __restrict__ X) {
    int bm = blockIdx.x;   // 0..511
    int bn = blockIdx.y;   // 0..5
    extern __shared__ float smem[];
    float* As = smem;                 // 2 * 128*32 floats
    float* Bs = smem + 2 * BM * BK;   // 2 * 32*64 floats

    int tid  = threadIdx.x;
    int lane = tid & 31;
    int warp = tid >> 5;
    int wm = warp & 3;   // 0..3  (M dir, 32 rows each)
    int wn = warp >> 2;  // 0..1  (N dir, 32 cols each)

    const float* Xtile = X + (size_t)bm * BM * KDIM;
    const float* Wtile = g_W1cat + bn * BN;

    float acc[2][4][4];
#pragma unroll
    for (int i = 0; i < 2; i++)
#pragma unroll
        for (int j = 0; j < 4; j++)
#pragma unroll
            for (int r = 0; r < 4; r++) acc[i][j][r] = 0.f;

    auto loadA = [&](int buf, int kt) {
        float* dst = As + buf * BM * BK;
        const float* src = Xtile + kt * BK;
#pragma unroll
        for (int it = 0; it < 4; it++) {
            int slot = tid + it * 256;           // 0..1023
            int r  = slot >> 3;                  // row 0..127
            int c4 = (slot & 7) << 2;            // col, multiple of 4
            int pc = c4 ^ ((r & 7) << 2);        // XOR swizzle (bits 2..4)
            cp16(dst + r * BK + pc, src + (size_t)r * KDIM + c4);
        }
    };
    auto loadB = [&](int buf, int kt) {
        float* dst = Bs + buf * BK * BN;
        const float* src = Wtile + (size_t)kt * BK * NCAT;
#pragma unroll
        for (int it = 0; it < 2; it++) {
            int slot = tid + it * 256;           // 0..511
            int r  = slot >> 4;                  // k row 0..31
            int c4 = (slot & 15) << 2;           // n col, multiple of 4
            int pc = c4 ^ ((r & 3) << 3);        // XOR swizzle (bits 3..4)
            cp16(dst + r * BN + pc, src + (size_t)r * NCAT + c4);
        }
    };

    loadA(0, 0); loadB(0, 0);
    asm volatile("cp.async.commit_group;\n");

    for (int kt = 0; kt < NKT; kt++) {
        int buf = kt & 1;
        if (kt + 1 < NKT) {
            loadA(buf ^ 1, kt + 1);
            loadB(buf ^ 1, kt + 1);
            asm volatile("cp.async.commit_group;\n");
            asm volatile("cp.async.wait_group 1;\n");
        } else {
            asm volatile("cp.async.wait_group 0;\n");
        }
        __syncthreads();

        const float* A0 = As + buf * BM * BK;
        const float* B0 = Bs + buf * BK * BN;

#pragma unroll
        for (int ks = 0; ks < 4; ks++) {
            uint32_t afr[2][4];
#pragma unroll
            for (int i = 0; i < 2; i++) {
                int row  = wm * 32 + i * 16 + (lane >> 2);
                int row8 = row + 8;
                int c0 = ks * 8 + (lane & 3);
                int c1 = c0 + 4;
                float a0 = A0[row  * BK + (c0 ^ ((row  & 7) << 2))];
                float a1 = A0[row8 * BK + (c0 ^ ((row8 & 7) << 2))];
                float a2 = A0[row  * BK + (c1 ^ ((row  & 7) << 2))];
                float a3 = A0[row8 * BK + (c1 ^ ((row8 & 7) << 2))];
                asm("cvt.rna.tf32.f32 %0, %1;" : "=r"(afr[i][0]) : "f"(a0));
                asm("cvt.rna.tf32.f32 %0, %1;" : "=r"(afr[i][1]) : "f"(a1));
                asm("cvt.rna.tf32.f32 %0, %1;" : "=r"(afr[i][2]) : "f"(a2));
                asm("cvt.rna.tf32.f32 %0, %1;" : "=r"(afr[i][3]) : "f"(a3));
            }
            uint32_t bfr[4][2];
#pragma unroll
            for (int j = 0; j < 4; j++) {
                int n  = wn * 32 + j * 8 + (lane >> 2);
                int k0 = ks * 8 + (lane & 3);
                int k1 = k0 + 4;
                bfr[j][0] = __float_as_uint(B0[k0 * BN + (n ^ ((k0 & 3) << 3))]);
                bfr[j][1] = __float_as_uint(B0[k1 * BN + (n ^ ((k1 & 3) << 3))]);
            }
#pragma unroll
            for (int i = 0; i < 2; i++)
#pragma unroll
                for (int j = 0; j < 4; j++) {
                    asm volatile(
                        "mma.sync.aligned.m16n8k8.row.col.f32.tf32.tf32.f32 "
                        "{%0,%1,%2,%3}, {%4,%5,%6,%7}, {%8,%9}, {%0,%1,%2,%3};\n"
                        : "+f"(acc[i][j][0]), "+f"(acc[i][j][1]),
                          "+f"(acc[i][j][2]), "+f"(acc[i][j][3])
                        : "r"(afr[i][0]), "r"(afr[i][1]), "r"(afr[i][2]), "r"(afr[i][3]),
                          "r"(bfr[j][0]), "r"(bfr[j][1]));
                }
        }
        __syncthreads();
    }

    // epilogue: + bias, relu, store
    size_t outbase = (size_t)bm * BM * NCAT + bn * BN;
#pragma unroll
    for (int i = 0; i < 2; i++) {
        int row = wm * 32 + i * 16 + (lane >> 2);
#pragma unroll
        for (int j = 0; j < 4; j++) {
            int col = wn * 32 + j * 8 + 2 * (lane & 3);
            float bv0 = g_b1cat[bn * BN + col];
            float bv1 = g_b1cat[bn * BN + col + 1];
            float2 v0 = make_float2(fmaxf(acc[i][j][0] + bv0, 0.f),
                                    fmaxf(acc[i][j][1] + bv1, 0.f));
            float2 v1 = make_float2(fmaxf(acc[i][j][2] + bv0, 0.f),
                                    fmaxf(acc[i][j][3] + bv1, 0.f));
            *(float2*)&g_Y1[outbase + (size_t)row * NCAT + col]       = v0;
            *(float2*)&g_Y1[outbase + (size_t)(row + 8) * NCAT + col] = v1;
        }
    }
}

// ---------------- stage 2+3: selected expert tail MLP ----------------
// smem layout (floats):
//  W2: sc@0(2048) st@2048(2048) wm@4096(8192) ch@12288(8192)
//  W3: sc@20480(32) st@20512(32) wm@20544(64) ch@20608(64)
//  b2: sc@20672(32) st@20704(32) wm@20736(64) ch@20800(64)
//  b3: @20864(4)
#define S2_FLOATS 20868

__global__ __launch_bounds__(256) void stage2_kernel(
    const int* __restrict__ labels,
    const float* __restrict__ W2_sc, const float* __restrict__ b2_sc,
    const float* __restrict__ W3_sc, const float* __restrict__ b3_sc,
    const float* __restrict__ W2_st, const float* __restrict__ b2_st,
    const float* __restrict__ W3_st, const float* __restrict__ b3_st,
    const float* __restrict__ W2_wm, const float* __restrict__ b2_wm,
    const float* __restrict__ W3_wm, const float* __restrict__ b3_wm,
    const float* __restrict__ W2_ch, const float* __restrict__ b2_ch,
    const float* __restrict__ W3_ch, const float* __restrict__ b3_ch,
    float* __restrict__ out) {
    extern __shared__ float s[];
    int tid = threadIdx.x;

    for (int i = tid; i < 2048; i += 256) s[i]         = W2_sc[i];
    for (int i = tid; i < 2048; i += 256) s[2048 + i]  = W2_st[i];
    for (int i = tid; i < 8192; i += 256) s[4096 + i]  = W2_wm[i];
    for (int i = tid; i < 8192; i += 256) s[12288 + i] = W2_ch[i];
    if (tid < 32) s[20480 + tid] = W3_sc[tid];
    if (tid < 32) s[20512 + tid] = W3_st[tid];
    if (tid < 64) s[20544 + tid] = W3_wm[tid];
    if (tid < 64) s[20608 + tid] = W3_ch[tid];
    if (tid < 32) s[20672 + tid] = b2_sc[tid];
    if (tid < 32) s[20704 + tid] = b2_st[tid];
    if (tid < 64) s[20736 + tid] = b2_wm[tid];
    if (tid < 64) s[20800 + tid] = b2_ch[tid];
    if (tid == 0) { s[20864] = b3_sc[0]; s[20865] = b3_st[0];
                    s[20866] = b3_wm[0]; s[20867] = b3_ch[0]; }
    __syncthreads();

    int lane = tid & 31, wid = tid >> 5;
    const int hs[4]    = {64, 64, 128, 128};
    const int h2s[4]   = {32, 32, 64, 64};
    const int yoffs[4] = {0, 64, 128, 256};
    const int w2o[4]   = {0, 2048, 4096, 12288};
    const int w3o[4]   = {20480, 20512, 20544, 20608};
    const int b2o[4]   = {20672, 20704, 20736, 20800};

    for (int row = blockIdx.x * 8 + wid; row < NROWS; row += gridDim.x * 8) {
        int lab = labels[row];
        bool valid = (lab >= 0) && (lab <= 3);
        int l  = valid ? lab : 0;
        int h  = hs[l];
        int h2 = h2s[l];
        const float* yrow = g_Y1 + (size_t)row * NCAT + yoffs[l];

        float y0 = yrow[lane];
        float y1 = yrow[32 + lane];
        float y2 = (h == 128) ? yrow[64 + lane] : 0.f;
        float y3 = (h == 128) ? yrow[96 + lane] : 0.f;

        float acc0 = s[b2o[l] + lane];
        float acc1 = (h2 == 64) ? s[b2o[l] + 32 + lane] : 0.f;
        const float* w2 = s + w2o[l];

        // c = 0,1 always; 2,3 only if h==128
#pragma unroll
        for (int c = 0; c < 4; c++) {
            if (c >= (h >> 5)) break;
            float yc = (c == 0) ? y0 : (c == 1) ? y1 : (c == 2) ? y2 : y3;
#pragma unroll
            for (int ii = 0; ii < 32; ii++) {
                float v = __shfl_sync(0xffffffffu, yc, ii);
                int i = c * 32 + ii;
                acc0 += v * w2[i * h2 + lane];
                if (h2 == 64) acc1 += v * w2[i * h2 + 32 + lane];
            }
        }
        acc0 = fmaxf(acc0, 0.f);
        acc1 = fmaxf(acc1, 0.f);

        float p = acc0 * s[w3o[l] + lane];
        if (h2 == 64) p += acc1 * s[w3o[l] + 32 + lane];
#pragma unroll
        for (int off = 16; off; off >>= 1)
            p += __shfl_xor_sync(0xffffffffu, p, off);

        if (lane == 0) out[row] = valid ? (p + s[20864 + l]) : 0.f;
    }
}

// ---------------- launch ----------------
extern "C" void kernel_launch(void* const* d_in, const int* in_sizes, int n_in,
                              void* d_out, int out_size) {
    const float* x      = (const float*)d_in[0];
    const int*   labels = (const int*)d_in[1];
    const float* W1_sc = (const float*)d_in[2],  *b1_sc = (const float*)d_in[3];
    const float* W2_sc = (const float*)d_in[4],  *b2_sc = (const float*)d_in[5];
    const float* W3_sc = (const float*)d_in[6],  *b3_sc = (const float*)d_in[7];
    const float* W1_st = (const float*)d_in[8],  *b1_st = (const float*)d_in[9];
    const float* W2_st = (const float*)d_in[10], *b2_st = (const float*)d_in[11];
    const float* W3_st = (const float*)d_in[12], *b3_st = (const float*)d_in[13];
    const float* W1_wm = (const float*)d_in[14], *b1_wm = (const float*)d_in[15];
    const float* W2_wm = (const float*)d_in[16], *b2_wm = (const float*)d_in[17];
    const float* W3_wm = (const float*)d_in[18], *b3_wm = (const float*)d_in[19];
    const float* W1_ch = (const float*)d_in[20], *b1_ch = (const float*)d_in[21];
    const float* W2_ch = (const float*)d_in[22], *b2_ch = (const float*)d_in[23];
    const float* W3_ch = (const float*)d_in[24], *b3_ch = (const float*)d_in[25];
    float* out = (float*)d_out;

    prep_kernel<<<256, 256>>>(W1_sc, b1_sc, W1_st, b1_st, W1_wm, b1_wm, W1_ch, b1_ch);

    dim3 grid1(NROWS / BM, NCAT / BN);   // 512 x 6
    size_t smem1 = (size_t)(2 * BM * BK + 2 * BK * BN) * sizeof(float);  // 49152
    gemm1_kernel<<<grid1, 256, smem1>>>(x);

    size_t smem2 = (size_t)S2_FLOATS * sizeof(float);  // ~83.5 KB
    cudaFuncSetAttribute(stage2_kernel, cudaFuncAttributeMaxDynamicSharedMemorySize,
                         (int)smem2);
    stage2_kernel<<<592, 256, smem2>>>(labels,
        W2_sc, b2_sc, W3_sc, b3_sc,
        W2_st, b2_st, W3_st, b3_st,
        W2_wm, b2_wm, W3_wm, b3_wm,
        W2_ch, b2_ch, W3_ch, b3_ch,
        out);
}

// round 2
// speedup vs baseline: 3.5779x; 3.5779x over previous
#include <cuda_runtime.h>
#include <stdint.h>

#define NROWS 65536
#define KDIM  2048
#define BM 128
#define BK 32
#define NKT (KDIM / BK)   // 64

// ---------------- device scratch ----------------
__device__ int g_cnt[4];
__device__ int g_perm[4][NROWS];   // 1 MB

// ---------------- helpers ----------------
__device__ __forceinline__ void cp16(float* dst, const float* src) {
    uint32_t d = (uint32_t)__cvta_generic_to_shared(dst);
    asm volatile("cp.async.ca.shared.global [%0], [%1], 16;\n" :: "r"(d), "l"(src));
}
__device__ __forceinline__ uint32_t f2tf(float x) {
    uint32_t u; asm("cvt.rna.tf32.f32 %0, %1;" : "=r"(u) : "f"(x)); return u;
}

// ---------------- bucket kernels ----------------
__global__ void zero_cnt_kernel() {
    if (threadIdx.x < 4) g_cnt[threadIdx.x] = 0;
}

__global__ void bucket_kernel(const int* __restrict__ labels, float* __restrict__ out) {
    int r = blockIdx.x * blockDim.x + threadIdx.x;
    if (r >= NROWS) return;
    int lab = labels[r];
    bool valid = (lab >= 0) && (lab <= 3);
    if (!valid) { out[r] = 0.f; lab = -1; }
    int lane = threadIdx.x & 31;
#pragma unroll
    for (int l = 0; l < 4; l++) {
        unsigned mask = __ballot_sync(0xffffffffu, lab == l);
        if (lab == l) {
            int leader = __ffs(mask) - 1;
            int myrank = __popc(mask & ((1u << lane) - 1));
            int basep = 0;
            if (lane == leader) basep = atomicAdd(&g_cnt[l], __popc(mask));
            basep = __shfl_sync(mask, basep, leader);
            g_perm[l][basep + myrank] = r;
        }
    }
}

// ---------------- fused expert kernel ----------------
// One CTA = 128 gathered rows, full 3-layer MLP for one expert.
// Layer 1: 128 x H x 2048 tf32 mma, double-buffered cp.async.
// Layer 2: 128 x H2 x H tf32 mma, h1 in smem (tf32-rounded), W2 in smem.
// Layer 3: scalar fp32 + warp reduce, scatter to out.
template<int H>
__global__ __launch_bounds__(256) void expert_kernel(
    const float* __restrict__ X, int ebase,
    const float* __restrict__ W1a, const float* __restrict__ b1a,
    const float* __restrict__ W2a, const float* __restrict__ b2a,
    const float* __restrict__ W3a, const float* __restrict__ b3a,
    const float* __restrict__ W1b, const float* __restrict__ b1b,
    const float* __restrict__ W2b, const float* __restrict__ b2b,
    const float* __restrict__ W3b, const float* __restrict__ b3b,
    float* __restrict__ out)
{
    constexpr int H2  = H / 2;
    constexpr int JB  = H / 16;    // layer-1 n8 blocks per warp (warp n-tile = H/2)
    constexpr int JB2 = H2 / 16;   // layer-2 n8 blocks per warp (warp n-tile = H2/2)

    int e = ebase + blockIdx.y;
    int count = g_cnt[e];
    int base = blockIdx.x * BM;
    if (base >= count) return;

    const float* W1 = blockIdx.y ? W1b : W1a;
    const float* b1 = blockIdx.y ? b1b : b1a;
    const float* W2 = blockIdx.y ? W2b : W2a;
    const float* b2 = blockIdx.y ? b2b : b2a;
    const float* W3 = blockIdx.y ? W3b : W3a;
    const float* b3 = blockIdx.y ? b3b : b3a;
    const int* perm = g_perm[e];

    extern __shared__ float smem[];
    float* As    = smem;                    // 2*128*32 = 8192 floats
    float* Bs    = As + 2 * BM * BK;        // 2*32*H
    float* sW2   = Bs + 2 * BK * H;         // H*H2 (tf32-rounded, swizzled)
    float* sW3   = sW2 + H * H2;            // H2
    float* sB2   = sW3 + H2;                // H2
    float* sPart = sB2 + H2;                // 128
    int*   sRow  = (int*)(sPart + 128);     // 128
    float* h1    = As;                      // reused after mainloop: 128*H floats

    int tid = threadIdx.x, lane = tid & 31, warp = tid >> 5;
    int wm = warp & 3, wn = warp >> 2;

    if (tid < BM) {
        int idx = base + tid;
        if (idx >= count) idx = count - 1;
        sRow[tid] = perm[idx];
    }
    // W2 -> smem, tf32-rounded + swizzled for B-fragment loads
    for (int i = tid; i < H * H2; i += 256) {
        int k = i / H2, n = i - k * H2;
        sW2[k * H2 + (n ^ ((k & 3) << 3))] = __uint_as_float(f2tf(W2[i]));
    }
    if (tid < H2) { sW3[tid] = W3[tid]; sB2[tid] = b2[tid]; }
    __syncthreads();

    // fixed gather rows for this thread's A-loader slots
    int rid[4];
#pragma unroll
    for (int it = 0; it < 4; it++) rid[it] = sRow[(tid + it * 256) >> 3];

    float acc[2][JB][4];
#pragma unroll
    for (int i = 0; i < 2; i++)
#pragma unroll
        for (int j = 0; j < JB; j++)
#pragma unroll
            for (int r = 0; r < 4; r++) acc[i][j][r] = 0.f;

    auto loadA = [&](int buf, int kt) {
        float* dst = As + buf * BM * BK;
#pragma unroll
        for (int it = 0; it < 4; it++) {
            int slot = tid + it * 256;
            int r  = slot >> 3;
            int c4 = (slot & 7) << 2;
            int pc = c4 ^ ((r & 7) << 2);
            cp16(dst + r * BK + pc, X + (size_t)rid[it] * KDIM + kt * BK + c4);
        }
    };
    auto loadB = [&](int buf, int kt) {
        float* dst = Bs + buf * BK * H;
        const float* src = W1 + (size_t)kt * BK * H;
#pragma unroll
        for (int it = 0; it < (BK * H) / 1024; it++) {
            int slot = tid + it * 256;
            int r  = slot / (H / 4);
            int c4 = (slot % (H / 4)) << 2;
            int pc = c4 ^ ((r & 3) << 3);
            cp16(dst + r * H + pc, src + r * H + c4);
        }
    };

    loadA(0, 0); loadB(0, 0);
    asm volatile("cp.async.commit_group;\n");

    for (int kt = 0; kt < NKT; kt++) {
        int buf = kt & 1;
        if (kt + 1 < NKT) {
            loadA(buf ^ 1, kt + 1);
            loadB(buf ^ 1, kt + 1);
            asm volatile("cp.async.commit_group;\n");
            asm volatile("cp.async.wait_group 1;\n");
        } else {
            asm volatile("cp.async.wait_group 0;\n");
        }
        __syncthreads();

        const float* A0 = As + buf * BM * BK;
        const float* B0 = Bs + buf * BK * H;

#pragma unroll
        for (int ks = 0; ks < 4; ks++) {
            uint32_t afr[2][4];
#pragma unroll
            for (int i = 0; i < 2; i++) {
                int row  = wm * 32 + i * 16 + (lane >> 2);
                int row8 = row + 8;
                int c0 = ks * 8 + (lane & 3);
                int c1 = c0 + 4;
                afr[i][0] = f2tf(A0[row  * BK + (c0 ^ ((row  & 7) << 2))]);
                afr[i][1] = f2tf(A0[row8 * BK + (c0 ^ ((row8 & 7) << 2))]);
                afr[i][2] = f2tf(A0[row  * BK + (c1 ^ ((row  & 7) << 2))]);
                afr[i][3] = f2tf(A0[row8 * BK + (c1 ^ ((row8 & 7) << 2))]);
            }
            uint32_t bfr[JB][2];
#pragma unroll
            for (int j = 0; j < JB; j++) {
                int n  = wn * (H / 2) + j * 8 + (lane >> 2);
                int k0 = ks * 8 + (lane & 3);
                int k1 = k0 + 4;
                bfr[j][0] = f2tf(B0[k0 * H + (n ^ ((k0 & 3) << 3))]);
                bfr[j][1] = f2tf(B0[k1 * H + (n ^ ((k1 & 3) << 3))]);
            }
#pragma unroll
            for (int i = 0; i < 2; i++)
#pragma unroll
                for (int j = 0; j < JB; j++) {
                    asm volatile(
                        "mma.sync.aligned.m16n8k8.row.col.f32.tf32.tf32.f32 "
                        "{%0,%1,%2,%3}, {%4,%5,%6,%7}, {%8,%9}, {%0,%1,%2,%3};\n"
                        : "+f"(acc[i][j][0]), "+f"(acc[i][j][1]),
                          "+f"(acc[i][j][2]), "+f"(acc[i][j][3])
                        : "r"(afr[i][0]), "r"(afr[i][1]), "r"(afr[i][2]), "r"(afr[i][3]),
                          "r"(bfr[j][0]), "r"(bfr[j][1]));
                }
        }
        __syncthreads();
    }

    // ---- layer-1 epilogue: +b1, relu, tf32-round, store h1 (swizzled A layout) ----
#pragma unroll
    for (int i = 0; i < 2; i++) {
        int row0 = wm * 32 + i * 16 + (lane >> 2);
        int row1 = row0 + 8;
#pragma unroll
        for (int j = 0; j < JB; j++) {
            int col = wn * (H / 2) + j * 8 + 2 * (lane & 3);
            float bv0 = b1[col], bv1 = b1[col + 1];
            h1[row0 * H + ((col)     ^ ((row0 & 7) << 2))] =
                __uint_as_float(f2tf(fmaxf(acc[i][j][0] + bv0, 0.f)));
            h1[row0 * H + ((col + 1) ^ ((row0 & 7) << 2))] =
                __uint_as_float(f2tf(fmaxf(acc[i][j][1] + bv1, 0.f)));
            h1[row1 * H + ((col)     ^ ((row1 & 7) << 2))] =
                __uint_as_float(f2tf(fmaxf(acc[i][j][2] + bv0, 0.f)));
            h1[row1 * H + ((col + 1) ^ ((row1 & 7) << 2))] =
                __uint_as_float(f2tf(fmaxf(acc[i][j][3] + bv1, 0.f)));
        }
    }
    __syncthreads();

    // ---- layer 2: acc2[128 x H2] = h1 @ W2 (tf32 mma) ----
    float acc2[2][JB2][4];
#pragma unroll
    for (int i = 0; i < 2; i++)
#pragma unroll
        for (int j = 0; j < JB2; j++)
#pragma unroll
            for (int r = 0; r < 4; r++) acc2[i][j][r] = 0.f;

#pragma unroll
    for (int ks = 0; ks < H / 8; ks++) {
        uint32_t afr[2][4];
#pragma unroll
        for (int i = 0; i < 2; i++) {
            int row  = wm * 32 + i * 16 + (lane >> 2);
            int row8 = row + 8;
            int c0 = ks * 8 + (lane & 3);
            int c1 = c0 + 4;
            afr[i][0] = __float_as_uint(h1[row  * H + (c0 ^ ((row  & 7) << 2))]);
            afr[i][1] = __float_as_uint(h1[row8 * H + (c0 ^ ((row8 & 7) << 2))]);
            afr[i][2] = __float_as_uint(h1[row  * H + (c1 ^ ((row  & 7) << 2))]);
            afr[i][3] = __float_as_uint(h1[row8 * H + (c1 ^ ((row8 & 7) << 2))]);
        }
        uint32_t bfr[JB2][2];
#pragma unroll
        for (int j = 0; j < JB2; j++) {
            int n  = wn * (H2 / 2) + j * 8 + (lane >> 2);
            int k0 = ks * 8 + (lane & 3);
            int k1 = k0 + 4;
            bfr[j][0] = __float_as_uint(sW2[k0 * H2 + (n ^ ((k0 & 3) << 3))]);
            bfr[j][1] = __float_as_uint(sW2[k1 * H2 + (n ^ ((k1 & 3) << 3))]);
        }
#pragma unroll
        for (int i = 0; i < 2; i++)
#pragma unroll
            for (int j = 0; j < JB2; j++) {
                asm volatile(
                    "mma.sync.aligned.m16n8k8.row.col.f32.tf32.tf32.f32 "
                    "{%0,%1,%2,%3}, {%4,%5,%6,%7}, {%8,%9}, {%0,%1,%2,%3};\n"
                    : "+f"(acc2[i][j][0]), "+f"(acc2[i][j][1]),
                      "+f"(acc2[i][j][2]), "+f"(acc2[i][j][3])
                    : "r"(afr[i][0]), "r"(afr[i][1]), "r"(afr[i][2]), "r"(afr[i][3]),
                      "r"(bfr[j][0]), "r"(bfr[j][1]));
            }
    }

    // ---- layer 3: +b2, relu, dot W3, reduce, +b3, scatter ----
    float p[4] = {0.f, 0.f, 0.f, 0.f};
#pragma unroll
    for (int i = 0; i < 2; i++)
#pragma unroll
        for (int j = 0; j < JB2; j++) {
            int col = wn * (H2 / 2) + j * 8 + 2 * (lane & 3);
            float w0 = sW3[col], w1 = sW3[col + 1];
            float c0 = sB2[col], c1 = sB2[col + 1];
            p[i * 2 + 0] += fmaxf(acc2[i][j][0] + c0, 0.f) * w0
                          + fmaxf(acc2[i][j][1] + c1, 0.f) * w1;
            p[i * 2 + 1] += fmaxf(acc2[i][j][2] + c0, 0.f) * w0
                          + fmaxf(acc2[i][j][3] + c1, 0.f) * w1;
        }
#pragma unroll
    for (int t = 0; t < 4; t++) {
        p[t] += __shfl_xor_sync(0xffffffffu, p[t], 1);
        p[t] += __shfl_xor_sync(0xffffffffu, p[t], 2);
    }
    if (wn == 0 && (lane & 3) == 0) {
#pragma unroll
        for (int i = 0; i < 2; i++)
#pragma unroll
            for (int hh = 0; hh < 2; hh++) {
                int m = wm * 32 + i * 16 + hh * 8 + (lane >> 2);
                sPart[m] = p[i * 2 + hh];
            }
    }
    __syncthreads();
    if (wn == 1 && (lane & 3) == 0) {
        float b3v = b3[0];
#pragma unroll
        for (int i = 0; i < 2; i++)
#pragma unroll
            for (int hh = 0; hh < 2; hh++) {
                int m = wm * 32 + i * 16 + hh * 8 + (lane >> 2);
                if (base + m < count)
                    out[sRow[m]] = sPart[m] + p[i * 2 + hh] + b3v;
            }
    }
}

// ---------------- launch ----------------
extern "C" void kernel_launch(void* const* d_in, const int* in_sizes, int n_in,
                              void* d_out, int out_size) {
    const float* x      = (const float*)d_in[0];
    const int*   labels = (const int*)d_in[1];
    const float* W1_sc = (const float*)d_in[2],  *b1_sc = (const float*)d_in[3];
    const float* W2_sc = (const float*)d_in[4],  *b2_sc = (const float*)d_in[5];
    const float* W3_sc = (const float*)d_in[6],  *b3_sc = (const float*)d_in[7];
    const float* W1_st = (const float*)d_in[8],  *b1_st = (const float*)d_in[9];
    const float* W2_st = (const float*)d_in[10], *b2_st = (const float*)d_in[11];
    const float* W3_st = (const float*)d_in[12], *b3_st = (const float*)d_in[13];
    const float* W1_wm = (const float*)d_in[14], *b1_wm = (const float*)d_in[15];
    const float* W2_wm = (const float*)d_in[16], *b2_wm = (const float*)d_in[17];
    const float* W3_wm = (const float*)d_in[18], *b3_wm = (const float*)d_in[19];
    const float* W1_ch = (const float*)d_in[20], *b1_ch = (const float*)d_in[21];
    const float* W2_ch = (const float*)d_in[22], *b2_ch = (const float*)d_in[23];
    const float* W3_ch = (const float*)d_in[24], *b3_ch = (const float*)d_in[25];
    float* out = (float*)d_out;

    zero_cnt_kernel<<<1, 32>>>();
    bucket_kernel<<<NROWS / 256, 256>>>(labels, out);

    // smem sizes (floats): GEMM bufs + W2 + W3 + b2 + part + rowids
    const size_t smem64  = (size_t)(8192 + 2 * 32 * 64  + 64 * 32  + 32 + 32 + 128 + 128) * 4;
    const size_t smem128 = (size_t)(8192 + 2 * 32 * 128 + 128 * 64 + 64 + 64 + 128 + 128) * 4;

    cudaFuncSetAttribute(expert_kernel<64>,  cudaFuncAttributeMaxDynamicSharedMemorySize,
                         (int)smem64);
    cudaFuncSetAttribute(expert_kernel<128>, cudaFuncAttributeMaxDynamicSharedMemorySize,
                         (int)smem128);

    dim3 grid(NROWS / BM, 2);  // 512 chunks x 2 experts per kernel

    expert_kernel<64><<<grid, 256, smem64>>>(x, 0,
        W1_sc, b1_sc, W2_sc, b2_sc, W3_sc, b3_sc,
        W1_st, b1_st, W2_st, b2_st, W3_st, b3_st,
        out);

    expert_kernel<128><<<grid, 256, smem128>>>(x, 2,
        W1_wm, b1_wm, W2_wm, b2_wm, W3_wm, b3_wm,
        W1_ch, b1_ch, W2_ch, b2_ch, W3_ch, b3_ch,
        out);
}